// round 1
// baseline (speedup 1.0000x reference)
#include <cuda_runtime.h>
#include <cuda_bf16.h>
#include <math.h>

// Problem constants (fixed by the dataset)
#define NN    20000        // nodes
#define EE    320000       // edges (before self loops)
#define ET    (EE + NN)    // edges incl self loops
#define FIN   128
#define HID   128
#define HEADS 4
#define DBIG  (HEADS * HID)   // 512
#define BGR   64
#define SLOPE 0.2f

// ----------------------------------------------------------------------------
// Scratch (device globals — no allocation allowed)
// ----------------------------------------------------------------------------
__device__ float g_xl[(size_t)NN * DBIG];
__device__ float g_xr[(size_t)NN * DBIG];
__device__ float g_h1[(size_t)NN * DBIG];
__device__ float g_h2[(size_t)NN * DBIG];
__device__ float g_h3[(size_t)NN * HID];
__device__ float g_logits[(size_t)ET * HEADS];
__device__ int   g_deg[NN];
__device__ int   g_off[NN + 1];
__device__ int   g_cursor[NN];
__device__ int   g_csr_src[ET];
__device__ float g_pool[BGR * HID];
__device__ float g_cnt[BGR];

// ----------------------------------------------------------------------------
// CSR build
// ----------------------------------------------------------------------------
__global__ void zero_kernel() {
    int i = blockIdx.x * blockDim.x + threadIdx.x;
    if (i < NN) g_deg[i] = 0;
    if (i < BGR * HID) g_pool[i] = 0.f;
    if (i < BGR) g_cnt[i] = 0.f;
}

__global__ void hist_kernel(const int* __restrict__ edst) {
    int e = blockIdx.x * blockDim.x + threadIdx.x;
    if (e >= ET) return;
    int d = (e < EE) ? edst[e] : (e - EE);
    atomicAdd(&g_deg[d], 1);
}

__global__ void scan_kernel() {
    __shared__ int part[1024];
    int t = threadIdx.x;
    const int chunk = (NN + 1023) / 1024;
    int beg = t * chunk;
    int end = beg + chunk; if (end > NN) end = NN;
    int s = 0;
    for (int i = beg; i < end; i++) s += g_deg[i];
    part[t] = s;
    __syncthreads();
    for (int o = 1; o < 1024; o <<= 1) {
        int v = (t >= o) ? part[t - o] : 0;
        __syncthreads();
        part[t] += v;
        __syncthreads();
    }
    int run = (t == 0) ? 0 : part[t - 1];
    for (int i = beg; i < end; i++) {
        g_off[i] = run;
        g_cursor[i] = run;
        run += g_deg[i];
    }
    if (t == 1023) g_off[NN] = part[1023];
}

__global__ void scatter_kernel(const int* __restrict__ esrc, const int* __restrict__ edst) {
    int e = blockIdx.x * blockDim.x + threadIdx.x;
    if (e >= ET) return;
    int s, d;
    if (e < EE) { s = esrc[e]; d = edst[e]; }
    else        { s = e - EE;  d = e - EE; }
    int pos = atomicAdd(&g_cursor[d], 1);
    g_csr_src[pos] = s;
}

// ----------------------------------------------------------------------------
// SGEMM: C[N,M] = A[N,K] @ W[K,M] + bias[M]
// BM=BN=128, BK=8, 256 threads, 8x8 per thread. Requires K%8==0, M%128==0.
// ----------------------------------------------------------------------------
__global__ __launch_bounds__(256, 2)
void sgemm_bias_kernel(const float* __restrict__ A, const float* __restrict__ W,
                       const float* __restrict__ bias, float* __restrict__ C,
                       int N, int K, int M) {
    __shared__ float As[8][128];
    __shared__ float Ws[8][128];
    int tid = threadIdx.x;
    int brow = blockIdx.y * 128;
    int bcol = blockIdx.x * 128;
    int tr = (tid / 16) * 8;
    int tc = (tid % 16) * 8;
    float acc[8][8];
#pragma unroll
    for (int i = 0; i < 8; i++)
#pragma unroll
        for (int j = 0; j < 8; j++) acc[i][j] = 0.f;

    int arow  = tid >> 1;          // 128 rows, 2 threads/row
    int acol4 = (tid & 1) * 4;
    int wrow  = tid >> 5;          // 8 rows, 32 threads/row
    int wcol4 = (tid & 31) * 4;

    for (int k0 = 0; k0 < K; k0 += 8) {
        float4 av = make_float4(0.f, 0.f, 0.f, 0.f);
        int gr = brow + arow;
        if (gr < N) av = *(const float4*)(A + (size_t)gr * K + k0 + acol4);
        As[acol4 + 0][arow] = av.x;
        As[acol4 + 1][arow] = av.y;
        As[acol4 + 2][arow] = av.z;
        As[acol4 + 3][arow] = av.w;
        float4 wv = *(const float4*)(W + (size_t)(k0 + wrow) * M + bcol + wcol4);
        *(float4*)(&Ws[wrow][wcol4]) = wv;
        __syncthreads();
#pragma unroll
        for (int k = 0; k < 8; k++) {
            float a[8], b[8];
#pragma unroll
            for (int i = 0; i < 8; i++) a[i] = As[k][tr + i];
#pragma unroll
            for (int j = 0; j < 8; j++) b[j] = Ws[k][tc + j];
#pragma unroll
            for (int i = 0; i < 8; i++)
#pragma unroll
                for (int j = 0; j < 8; j++) acc[i][j] += a[i] * b[j];
        }
        __syncthreads();
    }
#pragma unroll
    for (int i = 0; i < 8; i++) {
        int gr = brow + tr + i;
        if (gr < N) {
#pragma unroll
            for (int j = 0; j < 8; j++)
                C[(size_t)gr * M + bcol + tc + j] = acc[i][j] + bias[bcol + tc + j];
        }
    }
}

// ----------------------------------------------------------------------------
// GATv2 attention + aggregation. One block (128 threads) per destination node.
// ----------------------------------------------------------------------------
template <int H>
__global__ __launch_bounds__(128)
void gatv2_attn_kernel(const float* __restrict__ xl, const float* __restrict__ xr,
                       const float* __restrict__ att, const float* __restrict__ bias,
                       float* __restrict__ out) {
    constexpr int C = 128;
    constexpr int D = H * C;
    __shared__ float xr_s[D];
    __shared__ float att_s[D];
    __shared__ float wmax[4][H];
    __shared__ float smax[H];

    int i = blockIdx.x;
    int tid = threadIdx.x;
    int lane = tid & 31;
    int w = tid >> 5;

    for (int t = tid; t < D; t += 128) {
        xr_s[t]  = xr[(size_t)i * D + t];
        att_s[t] = att[t];
    }
    int s = g_off[i];
    int deg = g_off[i + 1] - s;
    __syncthreads();

    float lmax[H];
#pragma unroll
    for (int h = 0; h < H; h++) lmax[h] = -1e30f;

    // phase 1: logits + per-head max. Warps stride over edges.
    for (int j = w; j < deg; j += 4) {
        int src = g_csr_src[s + j];
        const float* xlr = xl + (size_t)src * D;
#pragma unroll
        for (int h = 0; h < H; h++) {
            float4 xv = *(const float4*)(xlr + h * C + lane * 4);
            float4 rv = *(const float4*)(&xr_s[h * C + lane * 4]);
            float4 av = *(const float4*)(&att_s[h * C + lane * 4]);
            float p = 0.f, e;
            e = xv.x + rv.x; e = e > 0.f ? e : SLOPE * e; p += av.x * e;
            e = xv.y + rv.y; e = e > 0.f ? e : SLOPE * e; p += av.y * e;
            e = xv.z + rv.z; e = e > 0.f ? e : SLOPE * e; p += av.z * e;
            e = xv.w + rv.w; e = e > 0.f ? e : SLOPE * e; p += av.w * e;
#pragma unroll
            for (int o = 16; o; o >>= 1) p += __shfl_xor_sync(0xffffffffu, p, o);
            if (lane == 0) g_logits[(size_t)(s + j) * H + h] = p;
            lmax[h] = fmaxf(lmax[h], p);
        }
    }
    if (lane == 0) {
#pragma unroll
        for (int h = 0; h < H; h++) wmax[w][h] = lmax[h];
    }
    __syncthreads();
    if (tid < H)
        smax[tid] = fmaxf(fmaxf(wmax[0][tid], wmax[1][tid]),
                          fmaxf(wmax[2][tid], wmax[3][tid]));
    __syncthreads();

    // phase 2: softmax-weighted aggregation. Thread tid owns channel tid of each head.
    float acc[H], denom[H], m[H];
#pragma unroll
    for (int h = 0; h < H; h++) { acc[h] = 0.f; denom[h] = 0.f; m[h] = smax[h]; }

    for (int j = 0; j < deg; j++) {
        int src = g_csr_src[s + j];
        const float* xlr = xl + (size_t)src * D;
#pragma unroll
        for (int h = 0; h < H; h++) {
            float wgt = __expf(g_logits[(size_t)(s + j) * H + h] - m[h]);
            denom[h] += wgt;
            acc[h] += wgt * xlr[h * C + tid];
        }
    }
#pragma unroll
    for (int h = 0; h < H; h++) {
        float v = acc[h] / denom[h] + bias[h * C + tid];
        out[(size_t)i * D + h * C + tid] = v > 0.f ? v : expm1f(v);
    }
}

// ----------------------------------------------------------------------------
// Pooling + MLP
// ----------------------------------------------------------------------------
__global__ void pool_kernel(const int* __restrict__ batch) {
    int i = blockIdx.x;
    int t = threadIdx.x;
    int b = batch[i];
    atomicAdd(&g_pool[b * HID + t], g_h3[(size_t)i * HID + t]);
    if (t == 0) atomicAdd(&g_cnt[b], 1.0f);
}

__global__ void mlp_kernel(const float* __restrict__ W1, const float* __restrict__ b1,
                           const float* __restrict__ W2, const float* __restrict__ b2,
                           float* __restrict__ out) {
    int g = blockIdx.x;
    int t = threadIdx.x;
    __shared__ float p[HID];
    __shared__ float hid[HID];
    __shared__ float red[HID];
    float c = fmaxf(g_cnt[g], 1.0f);
    p[t] = g_pool[g * HID + t] / c;
    __syncthreads();
    float a = 0.f;
    for (int k = 0; k < HID; k++) a += p[k] * W1[k * HID + t];
    hid[t] = fmaxf(a + b1[t], 0.f);
    __syncthreads();
    for (int o = 0; o < 2; o++) {
        red[t] = hid[t] * W2[t * 2 + o];
        __syncthreads();
        for (int stp = 64; stp; stp >>= 1) {
            if (t < stp) red[t] += red[t + stp];
            __syncthreads();
        }
        if (t == 0) out[g * 2 + o] = red[0] + b2[o];
        __syncthreads();
    }
}

// ----------------------------------------------------------------------------
// Launch
// ----------------------------------------------------------------------------
extern "C" void kernel_launch(void* const* d_in, const int* in_sizes, int n_in,
                              void* d_out, int out_size) {
    const float* x     = (const float*)d_in[0];
    const int*   esrc  = (const int*)d_in[1];
    const int*   edst  = (const int*)d_in[2];
    const int*   batch = (const int*)d_in[3];
    const float* Wl1 = (const float*)d_in[4];
    const float* Wr1 = (const float*)d_in[5];
    const float* bl1 = (const float*)d_in[6];
    const float* br1 = (const float*)d_in[7];
    const float* att1  = (const float*)d_in[8];
    const float* bias1 = (const float*)d_in[9];
    const float* Wl2 = (const float*)d_in[10];
    const float* Wr2 = (const float*)d_in[11];
    const float* bl2 = (const float*)d_in[12];
    const float* br2 = (const float*)d_in[13];
    const float* att2  = (const float*)d_in[14];
    const float* bias2 = (const float*)d_in[15];
    const float* Wl3 = (const float*)d_in[16];
    const float* Wr3 = (const float*)d_in[17];
    const float* bl3 = (const float*)d_in[18];
    const float* br3 = (const float*)d_in[19];
    const float* att3  = (const float*)d_in[20];
    const float* bias3 = (const float*)d_in[21];
    const float* Wm1 = (const float*)d_in[22];
    const float* bm1 = (const float*)d_in[23];
    const float* Wm2 = (const float*)d_in[24];
    const float* bm2 = (const float*)d_in[25];
    float* out = (float*)d_out;

    // Resolve device-global scratch addresses (host side)
    float *p_xl, *p_xr, *p_h1, *p_h2, *p_h3;
    cudaGetSymbolAddress((void**)&p_xl, g_xl);
    cudaGetSymbolAddress((void**)&p_xr, g_xr);
    cudaGetSymbolAddress((void**)&p_h1, g_h1);
    cudaGetSymbolAddress((void**)&p_h2, g_h2);
    cudaGetSymbolAddress((void**)&p_h3, g_h3);

    // CSR build
    zero_kernel<<<(NN + 255) / 256, 256>>>();
    hist_kernel<<<(ET + 255) / 256, 256>>>(edst);
    scan_kernel<<<1, 1024>>>();
    scatter_kernel<<<(ET + 255) / 256, 256>>>(esrc, edst);

    dim3 blk(256);
    dim3 grid_512(DBIG / 128, (NN + 127) / 128);  // M=512
    dim3 grid_128(HID / 128, (NN + 127) / 128);   // M=128

    // Layer 1
    sgemm_bias_kernel<<<grid_512, blk>>>(x, Wl1, bl1, p_xl, NN, FIN, DBIG);
    sgemm_bias_kernel<<<grid_512, blk>>>(x, Wr1, br1, p_xr, NN, FIN, DBIG);
    gatv2_attn_kernel<HEADS><<<NN, 128>>>(p_xl, p_xr, att1, bias1, p_h1);

    // Layer 2
    sgemm_bias_kernel<<<grid_512, blk>>>(p_h1, Wl2, bl2, p_xl, NN, DBIG, DBIG);
    sgemm_bias_kernel<<<grid_512, blk>>>(p_h1, Wr2, br2, p_xr, NN, DBIG, DBIG);
    gatv2_attn_kernel<HEADS><<<NN, 128>>>(p_xl, p_xr, att2, bias2, p_h2);

    // Layer 3 (H=1, out dim 128)
    sgemm_bias_kernel<<<grid_128, blk>>>(p_h2, Wl3, bl3, p_xl, NN, DBIG, HID);
    sgemm_bias_kernel<<<grid_128, blk>>>(p_h2, Wr3, br3, p_xr, NN, DBIG, HID);
    gatv2_attn_kernel<1><<<NN, 128>>>(p_xl, p_xr, att3, bias3, p_h3);

    // Pool + MLP
    pool_kernel<<<NN, HID>>>(batch);
    mlp_kernel<<<BGR, HID>>>(Wm1, bm1, Wm2, bm2, out);
}

// round 4
// speedup vs baseline: 2.0507x; 2.0507x over previous
#include <cuda_runtime.h>
#include <cuda_bf16.h>
#include <cstdint>
#include <math.h>

#define NN    20000
#define EE    320000
#define ET    (EE + NN)
#define FIN   128
#define HID   128
#define HEADS 4
#define DBIG  (HEADS * HID)
#define BGR   64
#define SLOPE 0.2f

// ----------------------------------------------------------------------------
// Scratch (device globals)
// ----------------------------------------------------------------------------
__device__ float g_xl[(size_t)NN * DBIG];
__device__ float g_xr[(size_t)NN * DBIG];
__device__ float g_h1[(size_t)NN * DBIG];
__device__ float g_h2[(size_t)NN * DBIG];
__device__ float g_h3[(size_t)NN * HID];
__device__ float g_wta[512 * 512];
__device__ float g_wtb[512 * 512];
__device__ int   g_deg[NN];
__device__ int   g_off[NN + 1];
__device__ int   g_cursor[NN];
__device__ int   g_csr_src[ET];
__device__ float g_pool[BGR * HID];
__device__ float g_cnt[BGR];

// ----------------------------------------------------------------------------
// Helpers
// ----------------------------------------------------------------------------
__device__ __forceinline__ uint32_t f2tf32(float f) {
    uint32_t u;
    asm("cvt.rna.tf32.f32 %0, %1;" : "=r"(u) : "f"(f));
    return u;
}

// ----------------------------------------------------------------------------
// CSR build
// ----------------------------------------------------------------------------
__global__ void zero_kernel() {
    int i = blockIdx.x * blockDim.x + threadIdx.x;
    if (i < NN) g_deg[i] = 0;
    if (i < BGR * HID) g_pool[i] = 0.f;
    if (i < BGR) g_cnt[i] = 0.f;
}
__global__ void hist_kernel(const int* __restrict__ edst) {
    int e = blockIdx.x * blockDim.x + threadIdx.x;
    if (e >= ET) return;
    int d = (e < EE) ? edst[e] : (e - EE);
    atomicAdd(&g_deg[d], 1);
}
__global__ void scan_kernel() {
    __shared__ int part[1024];
    int t = threadIdx.x;
    const int chunk = (NN + 1023) / 1024;
    int beg = t * chunk, end = beg + chunk;
    if (end > NN) end = NN;
    int s = 0;
    for (int i = beg; i < end; i++) s += g_deg[i];
    part[t] = s;
    __syncthreads();
    for (int o = 1; o < 1024; o <<= 1) {
        int v = (t >= o) ? part[t - o] : 0;
        __syncthreads();
        part[t] += v;
        __syncthreads();
    }
    int run = (t == 0) ? 0 : part[t - 1];
    for (int i = beg; i < end; i++) {
        g_off[i] = run; g_cursor[i] = run; run += g_deg[i];
    }
    if (t == 1023) g_off[NN] = part[1023];
}
__global__ void scatter_kernel(const int* __restrict__ esrc, const int* __restrict__ edst) {
    int e = blockIdx.x * blockDim.x + threadIdx.x;
    if (e >= ET) return;
    int s, d;
    if (e < EE) { s = esrc[e]; d = edst[e]; }
    else        { s = e - EE;  d = e - EE; }
    int pos = atomicAdd(&g_cursor[d], 1);
    g_csr_src[pos] = s;
}

// ----------------------------------------------------------------------------
// Weight transpose: WT[m][k] = W[k][m]
// ----------------------------------------------------------------------------
__global__ void transpose_kernel(const float* __restrict__ W, float* __restrict__ WT,
                                 int K, int M) {
    __shared__ float t[32][33];
    int m0 = blockIdx.x * 32, k0 = blockIdx.y * 32;
    int tx = threadIdx.x, ty = threadIdx.y;
#pragma unroll
    for (int i = 0; i < 32; i += 8)
        t[ty + i][tx] = W[(size_t)(k0 + ty + i) * M + m0 + tx];
    __syncthreads();
#pragma unroll
    for (int i = 0; i < 32; i += 8)
        WT[(size_t)(m0 + ty + i) * K + k0 + tx] = t[tx][ty + i];
}

// ----------------------------------------------------------------------------
// tf32 mma.sync GEMM: C[Nrows, Mout] = A[Nrows, K] @ BT^T + bias
// BM=128, BN=128, BK=32. 256 threads = 8 warps, warp tile 64x32.
// A row-major [N,K], BT row-major [Mout,K] (i.e. B col-major). K%32==0, Mout%128==0.
// ----------------------------------------------------------------------------
__global__ __launch_bounds__(256, 1)
void gemm_mma(const float* __restrict__ A, const float* __restrict__ BT,
              const float* __restrict__ bias, float* __restrict__ C,
              int Nrows, int K, int Mout) {
    __shared__ uint32_t As[128][36];
    __shared__ uint32_t Bs[128][36];

    int tid = threadIdx.x;
    int lane = tid & 31, wid = tid >> 5;
    int wm = wid & 1;        // 0..1 -> M offset 64*wm
    int wn = wid >> 1;       // 0..3 -> N offset 32*wn
    int g = lane >> 2, t = lane & 3;
    int brow = blockIdx.x * 128;
    int bcol = blockIdx.y * 128;

    float acc[4][4][4];
#pragma unroll
    for (int a = 0; a < 4; a++)
#pragma unroll
        for (int b = 0; b < 4; b++)
#pragma unroll
            for (int c = 0; c < 4; c++) acc[a][b][c] = 0.f;

    for (int k0 = 0; k0 < K; k0 += 32) {
        // A tile: 128 x 32
#pragma unroll
        for (int e = tid; e < 1024; e += 256) {
            int row = e >> 3, c4 = (e & 7) * 4;
            float4 v = make_float4(0.f, 0.f, 0.f, 0.f);
            int gr = brow + row;
            if (gr < Nrows) v = *(const float4*)(A + (size_t)gr * K + k0 + c4);
            As[row][c4 + 0] = f2tf32(v.x);
            As[row][c4 + 1] = f2tf32(v.y);
            As[row][c4 + 2] = f2tf32(v.z);
            As[row][c4 + 3] = f2tf32(v.w);
        }
        // B tile: 128 x 32 (BT rows = output cols)
#pragma unroll
        for (int e = tid; e < 1024; e += 256) {
            int row = e >> 3, c4 = (e & 7) * 4;
            float4 v = *(const float4*)(BT + (size_t)(bcol + row) * K + k0 + c4);
            Bs[row][c4 + 0] = f2tf32(v.x);
            Bs[row][c4 + 1] = f2tf32(v.y);
            Bs[row][c4 + 2] = f2tf32(v.z);
            Bs[row][c4 + 3] = f2tf32(v.w);
        }
        __syncthreads();

#pragma unroll
        for (int kk = 0; kk < 32; kk += 8) {
            uint32_t af[4][4], bf[4][2];
#pragma unroll
            for (int mt = 0; mt < 4; mt++) {
                int r = wm * 64 + mt * 16 + g;
                af[mt][0] = As[r][kk + t];
                af[mt][1] = As[r + 8][kk + t];
                af[mt][2] = As[r][kk + t + 4];
                af[mt][3] = As[r + 8][kk + t + 4];
            }
#pragma unroll
            for (int nt = 0; nt < 4; nt++) {
                int n = wn * 32 + nt * 8 + g;
                bf[nt][0] = Bs[n][kk + t];
                bf[nt][1] = Bs[n][kk + t + 4];
            }
#pragma unroll
            for (int mt = 0; mt < 4; mt++)
#pragma unroll
                for (int nt = 0; nt < 4; nt++) {
                    asm volatile(
                        "mma.sync.aligned.m16n8k8.row.col.f32.tf32.tf32.f32 "
                        "{%0,%1,%2,%3}, {%4,%5,%6,%7}, {%8,%9}, {%0,%1,%2,%3};"
                        : "+f"(acc[mt][nt][0]), "+f"(acc[mt][nt][1]),
                          "+f"(acc[mt][nt][2]), "+f"(acc[mt][nt][3])
                        : "r"(af[mt][0]), "r"(af[mt][1]), "r"(af[mt][2]), "r"(af[mt][3]),
                          "r"(bf[nt][0]), "r"(bf[nt][1]));
                }
        }
        __syncthreads();
    }

    // Epilogue: c0/c1 at (row=g, col=2t,2t+1), c2/c3 at row=g+8
#pragma unroll
    for (int mt = 0; mt < 4; mt++) {
        int r0 = brow + wm * 64 + mt * 16 + g;
#pragma unroll
        for (int nt = 0; nt < 4; nt++) {
            int c = bcol + wn * 32 + nt * 8 + 2 * t;
            float b0 = bias[c], b1 = bias[c + 1];
            if (r0 < Nrows) {
                float2 v = make_float2(acc[mt][nt][0] + b0, acc[mt][nt][1] + b1);
                *(float2*)(C + (size_t)r0 * Mout + c) = v;
            }
            if (r0 + 8 < Nrows) {
                float2 v = make_float2(acc[mt][nt][2] + b0, acc[mt][nt][3] + b1);
                *(float2*)(C + (size_t)(r0 + 8) * Mout + c) = v;
            }
        }
    }
}

// ----------------------------------------------------------------------------
// Fused GATv2 attention (online softmax): one warp per (node, head)
// ----------------------------------------------------------------------------
template <int H>
__global__ __launch_bounds__(256)
void gatv2_fused(const float* __restrict__ xl, const float* __restrict__ xr,
                 const float* __restrict__ att, const float* __restrict__ bias,
                 float* __restrict__ out) {
    int wg = blockIdx.x * 8 + (threadIdx.x >> 5);
    int node = wg / H;
    int h = wg % H;
    if (node >= NN) return;
    int lane = threadIdx.x & 31;
    const int D = H * 128;
    int cbase = h * 128 + lane * 4;

    float4 rv = *(const float4*)(xr + (size_t)node * D + cbase);
    float4 av = *(const float4*)(att + cbase);
    int s = g_off[node], e = g_off[node + 1];

    float m = -1e30f, den = 0.f;
    float4 acc = make_float4(0.f, 0.f, 0.f, 0.f);

    for (int j = s; j < e; j++) {
        int src = g_csr_src[j];
        float4 xv = *(const float4*)(xl + (size_t)src * D + cbase);
        float t, p = 0.f;
        t = xv.x + rv.x; t = t > 0.f ? t : SLOPE * t; p += av.x * t;
        t = xv.y + rv.y; t = t > 0.f ? t : SLOPE * t; p += av.y * t;
        t = xv.z + rv.z; t = t > 0.f ? t : SLOPE * t; p += av.z * t;
        t = xv.w + rv.w; t = t > 0.f ? t : SLOPE * t; p += av.w * t;
#pragma unroll
        for (int o = 16; o; o >>= 1) p += __shfl_xor_sync(0xffffffffu, p, o);
        if (p > m) {
            float sc = __expf(m - p);
            den *= sc; acc.x *= sc; acc.y *= sc; acc.z *= sc; acc.w *= sc;
            m = p;
        }
        float w = __expf(p - m);
        den += w;
        acc.x += w * xv.x; acc.y += w * xv.y; acc.z += w * xv.z; acc.w += w * xv.w;
    }
    float inv = 1.f / den;
    float4 o4;
    float v;
    v = acc.x * inv + bias[cbase + 0]; o4.x = v > 0.f ? v : expm1f(v);
    v = acc.y * inv + bias[cbase + 1]; o4.y = v > 0.f ? v : expm1f(v);
    v = acc.z * inv + bias[cbase + 2]; o4.z = v > 0.f ? v : expm1f(v);
    v = acc.w * inv + bias[cbase + 3]; o4.w = v > 0.f ? v : expm1f(v);
    *(float4*)(out + (size_t)node * D + cbase) = o4;
}

// ----------------------------------------------------------------------------
// Pooling + MLP
// ----------------------------------------------------------------------------
__global__ void pool_kernel(const int* __restrict__ batch) {
    int i = blockIdx.x;
    int t = threadIdx.x;
    int b = batch[i];
    atomicAdd(&g_pool[b * HID + t], g_h3[(size_t)i * HID + t]);
    if (t == 0) atomicAdd(&g_cnt[b], 1.0f);
}
__global__ void mlp_kernel(const float* __restrict__ W1, const float* __restrict__ b1,
                           const float* __restrict__ W2, const float* __restrict__ b2,
                           float* __restrict__ out) {
    int g = blockIdx.x;
    int t = threadIdx.x;
    __shared__ float p[HID];
    __shared__ float hid[HID];
    __shared__ float red[HID];
    float c = fmaxf(g_cnt[g], 1.0f);
    p[t] = g_pool[g * HID + t] / c;
    __syncthreads();
    float a = 0.f;
    for (int k = 0; k < HID; k++) a += p[k] * W1[k * HID + t];
    hid[t] = fmaxf(a + b1[t], 0.f);
    __syncthreads();
    for (int o = 0; o < 2; o++) {
        red[t] = hid[t] * W2[t * 2 + o];
        __syncthreads();
        for (int stp = 64; stp; stp >>= 1) {
            if (t < stp) red[t] += red[t + stp];
            __syncthreads();
        }
        if (t == 0) out[g * 2 + o] = red[0] + b2[o];
        __syncthreads();
    }
}

// ----------------------------------------------------------------------------
// Launch
// ----------------------------------------------------------------------------
extern "C" void kernel_launch(void* const* d_in, const int* in_sizes, int n_in,
                              void* d_out, int out_size) {
    const float* x     = (const float*)d_in[0];
    const int*   esrc  = (const int*)d_in[1];
    const int*   edst  = (const int*)d_in[2];
    const int*   batch = (const int*)d_in[3];
    const float* Wl1 = (const float*)d_in[4];
    const float* Wr1 = (const float*)d_in[5];
    const float* bl1 = (const float*)d_in[6];
    const float* br1 = (const float*)d_in[7];
    const float* att1  = (const float*)d_in[8];
    const float* bias1 = (const float*)d_in[9];
    const float* Wl2 = (const float*)d_in[10];
    const float* Wr2 = (const float*)d_in[11];
    const float* bl2 = (const float*)d_in[12];
    const float* br2 = (const float*)d_in[13];
    const float* att2  = (const float*)d_in[14];
    const float* bias2 = (const float*)d_in[15];
    const float* Wl3 = (const float*)d_in[16];
    const float* Wr3 = (const float*)d_in[17];
    const float* bl3 = (const float*)d_in[18];
    const float* br3 = (const float*)d_in[19];
    const float* att3  = (const float*)d_in[20];
    const float* bias3 = (const float*)d_in[21];
    const float* Wm1 = (const float*)d_in[22];
    const float* bm1 = (const float*)d_in[23];
    const float* Wm2 = (const float*)d_in[24];
    const float* bm2 = (const float*)d_in[25];
    float* out = (float*)d_out;

    float *p_xl, *p_xr, *p_h1, *p_h2, *p_h3, *p_wta, *p_wtb;
    cudaGetSymbolAddress((void**)&p_xl, g_xl);
    cudaGetSymbolAddress((void**)&p_xr, g_xr);
    cudaGetSymbolAddress((void**)&p_h1, g_h1);
    cudaGetSymbolAddress((void**)&p_h2, g_h2);
    cudaGetSymbolAddress((void**)&p_h3, g_h3);
    cudaGetSymbolAddress((void**)&p_wta, g_wta);
    cudaGetSymbolAddress((void**)&p_wtb, g_wtb);

    // CSR build
    zero_kernel<<<(NN + 255) / 256, 256>>>();
    hist_kernel<<<(ET + 255) / 256, 256>>>(edst);
    scan_kernel<<<1, 1024>>>();
    scatter_kernel<<<(ET + 255) / 256, 256>>>(esrc, edst);

    const int RT = (NN + 127) / 128;  // 157 row tiles
    dim3 tb(32, 8);

    // Layer 1: K=128 -> 512
    transpose_kernel<<<dim3(512 / 32, 128 / 32), tb>>>(Wl1, p_wta, 128, 512);
    transpose_kernel<<<dim3(512 / 32, 128 / 32), tb>>>(Wr1, p_wtb, 128, 512);
    gemm_mma<<<dim3(RT, 4), 256>>>(x, p_wta, bl1, p_xl, NN, 128, 512);
    gemm_mma<<<dim3(RT, 4), 256>>>(x, p_wtb, br1, p_xr, NN, 128, 512);
    gatv2_fused<HEADS><<<(NN * HEADS + 7) / 8, 256>>>(p_xl, p_xr, att1, bias1, p_h1);

    // Layer 2: 512 -> 512
    transpose_kernel<<<dim3(512 / 32, 512 / 32), tb>>>(Wl2, p_wta, 512, 512);
    transpose_kernel<<<dim3(512 / 32, 512 / 32), tb>>>(Wr2, p_wtb, 512, 512);
    gemm_mma<<<dim3(RT, 4), 256>>>(p_h1, p_wta, bl2, p_xl, NN, 512, 512);
    gemm_mma<<<dim3(RT, 4), 256>>>(p_h1, p_wtb, br2, p_xr, NN, 512, 512);
    gatv2_fused<HEADS><<<(NN * HEADS + 7) / 8, 256>>>(p_xl, p_xr, att2, bias2, p_h2);

    // Layer 3: 512 -> 128, single head
    transpose_kernel<<<dim3(128 / 32, 512 / 32), tb>>>(Wl3, p_wta, 512, 128);
    transpose_kernel<<<dim3(128 / 32, 512 / 32), tb>>>(Wr3, p_wtb, 512, 128);
    gemm_mma<<<dim3(RT, 1), 256>>>(p_h2, p_wta, bl3, p_xl, NN, 512, 128);
    gemm_mma<<<dim3(RT, 1), 256>>>(p_h2, p_wtb, br3, p_xr, NN, 512, 128);
    gatv2_fused<1><<<(NN + 7) / 8, 256>>>(p_xl, p_xr, att3, bias3, p_h3);

    // Pool + MLP
    pool_kernel<<<NN, HID>>>(batch);
    mlp_kernel<<<BGR, HID>>>(Wm1, bm1, Wm2, bm2, out);
}

// round 5
// speedup vs baseline: 2.6150x; 1.2752x over previous
#include <cuda_runtime.h>
#include <cuda_bf16.h>
#include <cstdint>
#include <math.h>

#define NN    20000
#define EE    320000
#define ET    (EE + NN)
#define FIN   128
#define HID   128
#define HEADS 4
#define DBIG  (HEADS * HID)
#define BGR   64
#define SLOPE 0.2f

// ----------------------------------------------------------------------------
// Scratch (device globals)
// ----------------------------------------------------------------------------
__device__ float g_xlr[(size_t)NN * 1024];   // fused [xl | xr] output
__device__ float g_h1[(size_t)NN * DBIG];
__device__ float g_h2[(size_t)NN * DBIG];
__device__ float g_h3[(size_t)NN * HID];
__device__ float g_wt[1024 * 512];           // fused transposed weights
__device__ int   g_deg[NN];
__device__ int   g_off[NN + 1];
__device__ int   g_cursor[NN];
__device__ int   g_csr_src[ET];
__device__ float g_pool[BGR * HID];
__device__ float g_cnt[BGR];

// ----------------------------------------------------------------------------
// Helpers
// ----------------------------------------------------------------------------
__device__ __forceinline__ uint32_t f2tf32(float f) {
    uint32_t u;
    asm("cvt.rna.tf32.f32 %0, %1;" : "=r"(u) : "f"(f));
    return u;
}
__device__ __forceinline__ uint32_t smem_u32(const void* p) {
    uint32_t a;
    asm("{ .reg .u64 t; cvta.to.shared.u64 t, %1; cvt.u32.u64 %0, t; }" : "=r"(a) : "l"(p));
    return a;
}
__device__ __forceinline__ void cp_async16(uint32_t dst, const void* src) {
    asm volatile("cp.async.cg.shared.global [%0], [%1], 16;" :: "r"(dst), "l"(src) : "memory");
}
__device__ __forceinline__ void cp_commit() {
    asm volatile("cp.async.commit_group;" ::: "memory");
}
template <int N>
__device__ __forceinline__ void cp_wait() {
    asm volatile("cp.async.wait_group %0;" :: "n"(N) : "memory");
}

// ----------------------------------------------------------------------------
// CSR build
// ----------------------------------------------------------------------------
__global__ void zero_kernel() {
    int i = blockIdx.x * blockDim.x + threadIdx.x;
    if (i < NN) g_deg[i] = 0;
    if (i < BGR * HID) g_pool[i] = 0.f;
    if (i < BGR) g_cnt[i] = 0.f;
}
__global__ void hist_kernel(const int* __restrict__ edst) {
    int e = blockIdx.x * blockDim.x + threadIdx.x;
    if (e >= ET) return;
    int d = (e < EE) ? edst[e] : (e - EE);
    atomicAdd(&g_deg[d], 1);
}
__global__ void scan_kernel() {
    __shared__ int part[1024];
    int t = threadIdx.x;
    const int chunk = (NN + 1023) / 1024;
    int beg = t * chunk, end = beg + chunk;
    if (end > NN) end = NN;
    int s = 0;
    for (int i = beg; i < end; i++) s += g_deg[i];
    part[t] = s;
    __syncthreads();
    for (int o = 1; o < 1024; o <<= 1) {
        int v = (t >= o) ? part[t - o] : 0;
        __syncthreads();
        part[t] += v;
        __syncthreads();
    }
    int run = (t == 0) ? 0 : part[t - 1];
    for (int i = beg; i < end; i++) {
        g_off[i] = run; g_cursor[i] = run; run += g_deg[i];
    }
    if (t == 1023) g_off[NN] = part[1023];
}
__global__ void scatter_kernel(const int* __restrict__ esrc, const int* __restrict__ edst) {
    int e = blockIdx.x * blockDim.x + threadIdx.x;
    if (e >= ET) return;
    int s, d;
    if (e < EE) { s = esrc[e]; d = edst[e]; }
    else        { s = e - EE;  d = e - EE; }
    int pos = atomicAdd(&g_cursor[d], 1);
    g_csr_src[pos] = s;
}

// ----------------------------------------------------------------------------
// Weight transpose: WT[m][k] = W[k][m]  (WT may be an offset into the fused buf)
// ----------------------------------------------------------------------------
__global__ void transpose_kernel(const float* __restrict__ W, float* __restrict__ WT,
                                 int K, int M) {
    __shared__ float t[32][33];
    int m0 = blockIdx.x * 32, k0 = blockIdx.y * 32;
    int tx = threadIdx.x, ty = threadIdx.y;
#pragma unroll
    for (int i = 0; i < 32; i += 8)
        t[ty + i][tx] = W[(size_t)(k0 + ty + i) * M + m0 + tx];
    __syncthreads();
#pragma unroll
    for (int i = 0; i < 32; i += 8)
        WT[(size_t)(m0 + ty + i) * K + k0 + tx] = t[tx][ty + i];
}

// ----------------------------------------------------------------------------
// tf32 mma.sync GEMM, cp.async double-buffered.
// C[Nrows, Mout] = A[Nrows, K] @ BT^T + [bias_l | bias_r]
// BM=128, BN=128, BK=32. 256 threads = 8 warps, warp tile 64x32.
// ----------------------------------------------------------------------------
#define SMEM_TILE (128 * 36)
__global__ __launch_bounds__(256, 2)
void gemm_mma(const float* __restrict__ A, const float* __restrict__ BT,
              const float* __restrict__ bias_l, const float* __restrict__ bias_r,
              float* __restrict__ C, int Nrows, int K, int Mout, int Mhalf) {
    extern __shared__ float sm[];
    float* smA = sm;                    // [2][128][36]
    float* smB = sm + 2 * SMEM_TILE;    // [2][128][36]
    uint32_t uA = smem_u32(smA);
    uint32_t uB = smem_u32(smB);

    int tid = threadIdx.x;
    int lane = tid & 31, wid = tid >> 5;
    int wm = wid & 1;
    int wn = wid >> 1;
    int g = lane >> 2, t = lane & 3;
    int brow = blockIdx.x * 128;
    int bcol = blockIdx.y * 128;

    int cprow = tid >> 3, cpc4 = (tid & 7) * 4;   // each thread: 4 rows apart x 1 float4

    float acc[4][4][4];
#pragma unroll
    for (int a = 0; a < 4; a++)
#pragma unroll
        for (int b = 0; b < 4; b++)
#pragma unroll
            for (int c = 0; c < 4; c++) acc[a][b][c] = 0.f;

    const int NT = K >> 5;

    // tile loader
    auto load_tile = [&](int kt, int buf) {
        int k0 = kt << 5;
#pragma unroll
        for (int i = 0; i < 4; i++) {
            int row = cprow + i * 32;
            int gr = brow + row; if (gr >= Nrows) gr = Nrows - 1;
            cp_async16(uA + (uint32_t)(buf * SMEM_TILE + row * 36 + cpc4) * 4,
                       A + (size_t)gr * K + k0 + cpc4);
        }
#pragma unroll
        for (int i = 0; i < 4; i++) {
            int row = cprow + i * 32;
            cp_async16(uB + (uint32_t)(buf * SMEM_TILE + row * 36 + cpc4) * 4,
                       BT + (size_t)(bcol + row) * K + k0 + cpc4);
        }
    };

    load_tile(0, 0);
    cp_commit();

    for (int kt = 0; kt < NT; kt++) {
        int buf = kt & 1;
        if (kt + 1 < NT) {
            load_tile(kt + 1, (kt + 1) & 1);
            cp_commit();
            cp_wait<1>();
        } else {
            cp_wait<0>();
        }
        __syncthreads();

        const float* Ab = smA + buf * SMEM_TILE;
        const float* Bb = smB + buf * SMEM_TILE;
#pragma unroll
        for (int kk = 0; kk < 32; kk += 8) {
            uint32_t af[4][4], bf[4][2];
#pragma unroll
            for (int mt = 0; mt < 4; mt++) {
                int r = wm * 64 + mt * 16 + g;
                af[mt][0] = f2tf32(Ab[r * 36 + kk + t]);
                af[mt][1] = f2tf32(Ab[(r + 8) * 36 + kk + t]);
                af[mt][2] = f2tf32(Ab[r * 36 + kk + t + 4]);
                af[mt][3] = f2tf32(Ab[(r + 8) * 36 + kk + t + 4]);
            }
#pragma unroll
            for (int nt = 0; nt < 4; nt++) {
                int n = wn * 32 + nt * 8 + g;
                bf[nt][0] = f2tf32(Bb[n * 36 + kk + t]);
                bf[nt][1] = f2tf32(Bb[n * 36 + kk + t + 4]);
            }
#pragma unroll
            for (int mt = 0; mt < 4; mt++)
#pragma unroll
                for (int nt = 0; nt < 4; nt++) {
                    asm volatile(
                        "mma.sync.aligned.m16n8k8.row.col.f32.tf32.tf32.f32 "
                        "{%0,%1,%2,%3}, {%4,%5,%6,%7}, {%8,%9}, {%0,%1,%2,%3};"
                        : "+f"(acc[mt][nt][0]), "+f"(acc[mt][nt][1]),
                          "+f"(acc[mt][nt][2]), "+f"(acc[mt][nt][3])
                        : "r"(af[mt][0]), "r"(af[mt][1]), "r"(af[mt][2]), "r"(af[mt][3]),
                          "r"(bf[nt][0]), "r"(bf[nt][1]));
                }
        }
        __syncthreads();
    }

    // Epilogue
#pragma unroll
    for (int mt = 0; mt < 4; mt++) {
        int r0 = brow + wm * 64 + mt * 16 + g;
#pragma unroll
        for (int nt = 0; nt < 4; nt++) {
            int c = bcol + wn * 32 + nt * 8 + 2 * t;
            float b0, b1;
            if (c < Mhalf) { b0 = bias_l[c]; b1 = bias_l[c + 1]; }
            else           { b0 = bias_r[c - Mhalf]; b1 = bias_r[c - Mhalf + 1]; }
            if (r0 < Nrows) {
                float2 v = make_float2(acc[mt][nt][0] + b0, acc[mt][nt][1] + b1);
                *(float2*)(C + (size_t)r0 * Mout + c) = v;
            }
            if (r0 + 8 < Nrows) {
                float2 v = make_float2(acc[mt][nt][2] + b0, acc[mt][nt][3] + b1);
                *(float2*)(C + (size_t)(r0 + 8) * Mout + c) = v;
            }
        }
    }
}

// ----------------------------------------------------------------------------
// Fused GATv2 attention (online softmax): one warp per (node, head).
// xlr rows: [xl(H*128) | xr(H*128)], row stride = 2*H*128.
// ----------------------------------------------------------------------------
template <int H>
__global__ __launch_bounds__(256)
void gatv2_fused(const float* __restrict__ xlr,
                 const float* __restrict__ att, const float* __restrict__ bias,
                 float* __restrict__ out) {
    const int S = 2 * H * 128;   // xlr row stride
    const int D = H * 128;       // out row stride / xr offset
    int wg = blockIdx.x * 8 + (threadIdx.x >> 5);
    int node = wg / H;
    int h = wg % H;
    if (node >= NN) return;
    int lane = threadIdx.x & 31;
    int cbase = h * 128 + lane * 4;

    float4 rv = *(const float4*)(xlr + (size_t)node * S + D + cbase);
    float4 av = *(const float4*)(att + cbase);
    int s = g_off[node], e = g_off[node + 1];

    float m = -1e30f, den = 0.f;
    float4 acc = make_float4(0.f, 0.f, 0.f, 0.f);

    for (int j = s; j < e; j++) {
        int src = g_csr_src[j];
        float4 xv = *(const float4*)(xlr + (size_t)src * S + cbase);
        float t, p = 0.f;
        t = xv.x + rv.x; t = t > 0.f ? t : SLOPE * t; p += av.x * t;
        t = xv.y + rv.y; t = t > 0.f ? t : SLOPE * t; p += av.y * t;
        t = xv.z + rv.z; t = t > 0.f ? t : SLOPE * t; p += av.z * t;
        t = xv.w + rv.w; t = t > 0.f ? t : SLOPE * t; p += av.w * t;
#pragma unroll
        for (int o = 16; o; o >>= 1) p += __shfl_xor_sync(0xffffffffu, p, o);
        if (p > m) {
            float sc = __expf(m - p);
            den *= sc; acc.x *= sc; acc.y *= sc; acc.z *= sc; acc.w *= sc;
            m = p;
        }
        float w = __expf(p - m);
        den += w;
        acc.x += w * xv.x; acc.y += w * xv.y; acc.z += w * xv.z; acc.w += w * xv.w;
    }
    float inv = 1.f / den;
    float4 o4;
    float v;
    v = acc.x * inv + bias[cbase + 0]; o4.x = v > 0.f ? v : expm1f(v);
    v = acc.y * inv + bias[cbase + 1]; o4.y = v > 0.f ? v : expm1f(v);
    v = acc.z * inv + bias[cbase + 2]; o4.z = v > 0.f ? v : expm1f(v);
    v = acc.w * inv + bias[cbase + 3]; o4.w = v > 0.f ? v : expm1f(v);
    *(float4*)(out + (size_t)node * D + cbase) = o4;
}

// ----------------------------------------------------------------------------
// Pooling + MLP
// ----------------------------------------------------------------------------
__global__ void pool_kernel(const int* __restrict__ batch) {
    int i = blockIdx.x;
    int t = threadIdx.x;
    int b = batch[i];
    atomicAdd(&g_pool[b * HID + t], g_h3[(size_t)i * HID + t]);
    if (t == 0) atomicAdd(&g_cnt[b], 1.0f);
}
__global__ void mlp_kernel(const float* __restrict__ W1, const float* __restrict__ b1,
                           const float* __restrict__ W2, const float* __restrict__ b2,
                           float* __restrict__ out) {
    int g = blockIdx.x;
    int t = threadIdx.x;
    __shared__ float p[HID];
    __shared__ float hid[HID];
    __shared__ float red[HID];
    float c = fmaxf(g_cnt[g], 1.0f);
    p[t] = g_pool[g * HID + t] / c;
    __syncthreads();
    float a = 0.f;
    for (int k = 0; k < HID; k++) a += p[k] * W1[k * HID + t];
    hid[t] = fmaxf(a + b1[t], 0.f);
    __syncthreads();
    for (int o = 0; o < 2; o++) {
        red[t] = hid[t] * W2[t * 2 + o];
        __syncthreads();
        for (int stp = 64; stp; stp >>= 1) {
            if (t < stp) red[t] += red[t + stp];
            __syncthreads();
        }
        if (t == 0) out[g * 2 + o] = red[0] + b2[o];
        __syncthreads();
    }
}

// ----------------------------------------------------------------------------
// Launch
// ----------------------------------------------------------------------------
extern "C" void kernel_launch(void* const* d_in, const int* in_sizes, int n_in,
                              void* d_out, int out_size) {
    const float* x     = (const float*)d_in[0];
    const int*   esrc  = (const int*)d_in[1];
    const int*   edst  = (const int*)d_in[2];
    const int*   batch = (const int*)d_in[3];
    const float* Wl1 = (const float*)d_in[4];
    const float* Wr1 = (const float*)d_in[5];
    const float* bl1 = (const float*)d_in[6];
    const float* br1 = (const float*)d_in[7];
    const float* att1  = (const float*)d_in[8];
    const float* bias1 = (const float*)d_in[9];
    const float* Wl2 = (const float*)d_in[10];
    const float* Wr2 = (const float*)d_in[11];
    const float* bl2 = (const float*)d_in[12];
    const float* br2 = (const float*)d_in[13];
    const float* att2  = (const float*)d_in[14];
    const float* bias2 = (const float*)d_in[15];
    const float* Wl3 = (const float*)d_in[16];
    const float* Wr3 = (const float*)d_in[17];
    const float* bl3 = (const float*)d_in[18];
    const float* br3 = (const float*)d_in[19];
    const float* att3  = (const float*)d_in[20];
    const float* bias3 = (const float*)d_in[21];
    const float* Wm1 = (const float*)d_in[22];
    const float* bm1 = (const float*)d_in[23];
    const float* Wm2 = (const float*)d_in[24];
    const float* bm2 = (const float*)d_in[25];
    float* out = (float*)d_out;

    float *p_xlr, *p_h1, *p_h2, *p_h3, *p_wt;
    cudaGetSymbolAddress((void**)&p_xlr, g_xlr);
    cudaGetSymbolAddress((void**)&p_h1, g_h1);
    cudaGetSymbolAddress((void**)&p_h2, g_h2);
    cudaGetSymbolAddress((void**)&p_h3, g_h3);
    cudaGetSymbolAddress((void**)&p_wt, g_wt);

    const int SMEM = 4 * SMEM_TILE * 4;  // 73728 bytes
    cudaFuncSetAttribute(gemm_mma, cudaFuncAttributeMaxDynamicSharedMemorySize, SMEM);

    // CSR build
    zero_kernel<<<(NN + 255) / 256, 256>>>();
    hist_kernel<<<(ET + 255) / 256, 256>>>(edst);
    scan_kernel<<<1, 1024>>>();
    scatter_kernel<<<(ET + 255) / 256, 256>>>(esrc, edst);

    const int RT = (NN + 127) / 128;  // 157 row tiles
    dim3 tb(32, 8);

    // Layer 1: K=128, fused Mout=1024
    transpose_kernel<<<dim3(16, 4), tb>>>(Wl1, p_wt, 128, 512);
    transpose_kernel<<<dim3(16, 4), tb>>>(Wr1, p_wt + 512 * 128, 128, 512);
    gemm_mma<<<dim3(RT, 8), 256, SMEM>>>(x, p_wt, bl1, br1, p_xlr, NN, 128, 1024, 512);
    gatv2_fused<HEADS><<<(NN * HEADS + 7) / 8, 256>>>(p_xlr, att1, bias1, p_h1);

    // Layer 2: K=512, fused Mout=1024
    transpose_kernel<<<dim3(16, 16), tb>>>(Wl2, p_wt, 512, 512);
    transpose_kernel<<<dim3(16, 16), tb>>>(Wr2, p_wt + 512 * 512, 512, 512);
    gemm_mma<<<dim3(RT, 8), 256, SMEM>>>(p_h1, p_wt, bl2, br2, p_xlr, NN, 512, 1024, 512);
    gatv2_fused<HEADS><<<(NN * HEADS + 7) / 8, 256>>>(p_xlr, att2, bias2, p_h2);

    // Layer 3: K=512, fused Mout=256, single head
    transpose_kernel<<<dim3(4, 16), tb>>>(Wl3, p_wt, 512, 128);
    transpose_kernel<<<dim3(4, 16), tb>>>(Wr3, p_wt + 128 * 512, 512, 128);
    gemm_mma<<<dim3(RT, 2), 256, SMEM>>>(p_h2, p_wt, bl3, br3, p_xlr, NN, 512, 256, 128);
    gatv2_fused<1><<<(NN + 7) / 8, 256>>>(p_xlr, att3, bias3, p_h3);

    // Pool + MLP
    pool_kernel<<<NN, HID>>>(batch);
    mlp_kernel<<<BGR, HID>>>(Wm1, bm1, Wm2, bm2, out);
}

// round 6
// speedup vs baseline: 2.8019x; 1.0715x over previous
#include <cuda_runtime.h>
#include <cuda_bf16.h>
#include <cstdint>
#include <math.h>

#define NN    20000
#define EE    320000
#define ET    (EE + NN)
#define FIN   128
#define HID   128
#define HEADS 4
#define DBIG  (HEADS * HID)
#define BGR   64
#define SLOPE 0.2f

// ----------------------------------------------------------------------------
// Scratch (device globals)
// ----------------------------------------------------------------------------
__device__ float g_xlr[(size_t)NN * 1024];   // fused [xl | xr] output (natural order)
__device__ float g_h1[(size_t)NN * DBIG];    // K-permuted + tf32-rounded
__device__ float g_h2[(size_t)NN * DBIG];    // K-permuted + tf32-rounded
__device__ float g_h3[(size_t)NN * HID];     // natural
__device__ float g_xp[(size_t)NN * FIN];     // x, K-permuted + tf32-rounded
__device__ float g_wt[1024 * 512];           // fused transposed weights (K-permuted, tf32)
__device__ int   g_deg[NN];
__device__ int   g_off[NN + 1];
__device__ int   g_cursor[NN];
__device__ int   g_csr_src[ET];
__device__ float g_pool[BGR * HID];
__device__ float g_cnt[BGR];

// ----------------------------------------------------------------------------
// Helpers
// ----------------------------------------------------------------------------
__device__ __forceinline__ uint32_t f2tf32(float f) {
    uint32_t u;
    asm("cvt.rna.tf32.f32 %0, %1;" : "=r"(u) : "f"(f));
    return u;
}
__device__ __forceinline__ float f2tf32f(float f) { return __uint_as_float(f2tf32(f)); }
// K-permutation within each 8-group: [0,4,1,5,2,6,3,7]
__device__ __forceinline__ int kperm(int k) {
    return (k & ~7) | (((k & 3) << 1) | ((k >> 2) & 1));
}
__device__ __forceinline__ uint32_t smem_u32(const void* p) {
    uint32_t a;
    asm("{ .reg .u64 t; cvta.to.shared.u64 t, %1; cvt.u32.u64 %0, t; }" : "=r"(a) : "l"(p));
    return a;
}
__device__ __forceinline__ void cp_async16(uint32_t dst, const void* src) {
    asm volatile("cp.async.cg.shared.global [%0], [%1], 16;" :: "r"(dst), "l"(src) : "memory");
}
__device__ __forceinline__ void cp_commit() {
    asm volatile("cp.async.commit_group;" ::: "memory");
}
template <int N>
__device__ __forceinline__ void cp_wait() {
    asm volatile("cp.async.wait_group %0;" :: "n"(N) : "memory");
}

// ----------------------------------------------------------------------------
// CSR build
// ----------------------------------------------------------------------------
__global__ void zero_kernel() {
    int i = blockIdx.x * blockDim.x + threadIdx.x;
    if (i < NN) g_deg[i] = 0;
    if (i < BGR * HID) g_pool[i] = 0.f;
    if (i < BGR) g_cnt[i] = 0.f;
}
__global__ void hist_kernel(const int* __restrict__ edst) {
    int e = blockIdx.x * blockDim.x + threadIdx.x;
    if (e >= ET) return;
    int d = (e < EE) ? edst[e] : (e - EE);
    atomicAdd(&g_deg[d], 1);
}
__global__ void scan_kernel() {
    __shared__ int part[1024];
    int t = threadIdx.x;
    const int chunk = (NN + 1023) / 1024;
    int beg = t * chunk, end = beg + chunk;
    if (end > NN) end = NN;
    int s = 0;
    for (int i = beg; i < end; i++) s += g_deg[i];
    part[t] = s;
    __syncthreads();
    for (int o = 1; o < 1024; o <<= 1) {
        int v = (t >= o) ? part[t - o] : 0;
        __syncthreads();
        part[t] += v;
        __syncthreads();
    }
    int run = (t == 0) ? 0 : part[t - 1];
    for (int i = beg; i < end; i++) {
        g_off[i] = run; g_cursor[i] = run; run += g_deg[i];
    }
    if (t == 1023) g_off[NN] = part[1023];
}
__global__ void scatter_kernel(const int* __restrict__ esrc, const int* __restrict__ edst) {
    int e = blockIdx.x * blockDim.x + threadIdx.x;
    if (e >= ET) return;
    int s, d;
    if (e < EE) { s = esrc[e]; d = edst[e]; }
    else        { s = e - EE;  d = e - EE; }
    int pos = atomicAdd(&g_cursor[d], 1);
    g_csr_src[pos] = s;
}

// ----------------------------------------------------------------------------
// x pre-pass: permute K within 8-groups + round to tf32
// ----------------------------------------------------------------------------
__global__ void permute_x_kernel(const float* __restrict__ x, float* __restrict__ xp) {
    int idx = blockIdx.x * blockDim.x + threadIdx.x;
    if (idx >= NN * FIN) return;
    int row = idx >> 7, k = idx & 127;
    xp[(size_t)row * FIN + kperm(k)] = f2tf32f(x[idx]);
}

// ----------------------------------------------------------------------------
// Weight transpose: WT[m][kperm(k)] = tf32(W[k][m])
// ----------------------------------------------------------------------------
__global__ void transpose_kernel(const float* __restrict__ W, float* __restrict__ WT,
                                 int K, int M) {
    __shared__ float t[32][33];
    int m0 = blockIdx.x * 32, k0 = blockIdx.y * 32;
    int tx = threadIdx.x, ty = threadIdx.y;
#pragma unroll
    for (int i = 0; i < 32; i += 8)
        t[ty + i][tx] = W[(size_t)(k0 + ty + i) * M + m0 + tx];
    __syncthreads();
    int kp = kperm(k0 + tx);
#pragma unroll
    for (int i = 0; i < 32; i += 8)
        WT[(size_t)(m0 + ty + i) * K + kp] = f2tf32f(t[tx][ty + i]);
}

// ----------------------------------------------------------------------------
// tf32 mma.sync GEMM, cp.async double-buffered, fragment-major K layout.
// A and BT are K-permuted + tf32-rounded. C natural order.
// BM=128, BN=128, BK=32. 256 threads = 8 warps, warp tile 64x32.
// ----------------------------------------------------------------------------
#define SM_STRIDE 40
#define SMEM_TILE (128 * SM_STRIDE)
__global__ __launch_bounds__(256, 2)
void gemm_mma(const float* __restrict__ A, const float* __restrict__ BT,
              const float* __restrict__ bias_l, const float* __restrict__ bias_r,
              float* __restrict__ C, int Nrows, int K, int Mout, int Mhalf) {
    extern __shared__ float sm[];
    float* smA = sm;                    // [2][128][40]
    float* smB = sm + 2 * SMEM_TILE;    // [2][128][40]
    uint32_t uA = smem_u32(smA);
    uint32_t uB = smem_u32(smB);

    int tid = threadIdx.x;
    int lane = tid & 31, wid = tid >> 5;
    int wm = wid & 1;
    int wn = wid >> 1;
    int g = lane >> 2, t = lane & 3;
    int brow = blockIdx.x * 128;
    int bcol = blockIdx.y * 128;

    int cprow = tid >> 3, cpc4 = (tid & 7) * 4;

    float acc[4][4][4];
#pragma unroll
    for (int a = 0; a < 4; a++)
#pragma unroll
        for (int b = 0; b < 4; b++)
#pragma unroll
            for (int c = 0; c < 4; c++) acc[a][b][c] = 0.f;

    const int NT = K >> 5;

    auto load_tile = [&](int kt, int buf) {
        int k0 = kt << 5;
#pragma unroll
        for (int i = 0; i < 4; i++) {
            int row = cprow + i * 32;
            int gr = brow + row; if (gr >= Nrows) gr = Nrows - 1;
            cp_async16(uA + (uint32_t)(buf * SMEM_TILE + row * SM_STRIDE + cpc4) * 4,
                       A + (size_t)gr * K + k0 + cpc4);
        }
#pragma unroll
        for (int i = 0; i < 4; i++) {
            int row = cprow + i * 32;
            cp_async16(uB + (uint32_t)(buf * SMEM_TILE + row * SM_STRIDE + cpc4) * 4,
                       BT + (size_t)(bcol + row) * K + k0 + cpc4);
        }
    };

    load_tile(0, 0);
    cp_commit();

    for (int kt = 0; kt < NT; kt++) {
        int buf = kt & 1;
        if (kt + 1 < NT) {
            load_tile(kt + 1, (kt + 1) & 1);
            cp_commit();
            cp_wait<1>();
        } else {
            cp_wait<0>();
        }
        __syncthreads();

        const float* Ab = smA + buf * SMEM_TILE;
        const float* Bb = smB + buf * SMEM_TILE;
#pragma unroll
        for (int kk = 0; kk < 32; kk += 8) {
            uint32_t af[4][4], bf[4][2];
#pragma unroll
            for (int mt = 0; mt < 4; mt++) {
                int r = wm * 64 + mt * 16 + g;
                // permuted layout: (k=t, k=t+4) contiguous at col 2t
                uint2 x0 = *(const uint2*)(Ab + r * SM_STRIDE + kk + 2 * t);
                uint2 x1 = *(const uint2*)(Ab + (r + 8) * SM_STRIDE + kk + 2 * t);
                af[mt][0] = x0.x;  // [r][t]
                af[mt][1] = x1.x;  // [r+8][t]
                af[mt][2] = x0.y;  // [r][t+4]
                af[mt][3] = x1.y;  // [r+8][t+4]
            }
#pragma unroll
            for (int nt = 0; nt < 4; nt++) {
                int n = wn * 32 + nt * 8 + g;
                uint2 b = *(const uint2*)(Bb + n * SM_STRIDE + kk + 2 * t);
                bf[nt][0] = b.x;
                bf[nt][1] = b.y;
            }
#pragma unroll
            for (int mt = 0; mt < 4; mt++)
#pragma unroll
                for (int nt = 0; nt < 4; nt++) {
                    asm volatile(
                        "mma.sync.aligned.m16n8k8.row.col.f32.tf32.tf32.f32 "
                        "{%0,%1,%2,%3}, {%4,%5,%6,%7}, {%8,%9}, {%0,%1,%2,%3};"
                        : "+f"(acc[mt][nt][0]), "+f"(acc[mt][nt][1]),
                          "+f"(acc[mt][nt][2]), "+f"(acc[mt][nt][3])
                        : "r"(af[mt][0]), "r"(af[mt][1]), "r"(af[mt][2]), "r"(af[mt][3]),
                          "r"(bf[nt][0]), "r"(bf[nt][1]));
                }
        }
        __syncthreads();
    }

    // Epilogue
#pragma unroll
    for (int mt = 0; mt < 4; mt++) {
        int r0 = brow + wm * 64 + mt * 16 + g;
#pragma unroll
        for (int nt = 0; nt < 4; nt++) {
            int c = bcol + wn * 32 + nt * 8 + 2 * t;
            float b0, b1;
            if (c < Mhalf) { b0 = bias_l[c]; b1 = bias_l[c + 1]; }
            else           { b0 = bias_r[c - Mhalf]; b1 = bias_r[c - Mhalf + 1]; }
            if (r0 < Nrows) {
                float2 v = make_float2(acc[mt][nt][0] + b0, acc[mt][nt][1] + b1);
                *(float2*)(C + (size_t)r0 * Mout + c) = v;
            }
            if (r0 + 8 < Nrows) {
                float2 v = make_float2(acc[mt][nt][2] + b0, acc[mt][nt][3] + b1);
                *(float2*)(C + (size_t)(r0 + 8) * Mout + c) = v;
            }
        }
    }
}

// ----------------------------------------------------------------------------
// Fused GATv2 attention (online softmax): one warp per (node, head).
// xlr rows: [xl(H*128) | xr(H*128)], stride 2*H*128 (natural order).
// If PERM: output written K-permuted + tf32-rounded (for next GEMM).
// ----------------------------------------------------------------------------
template <int H, bool PERM>
__global__ __launch_bounds__(256)
void gatv2_fused(const float* __restrict__ xlr,
                 const float* __restrict__ att, const float* __restrict__ bias,
                 float* __restrict__ out) {
    const int S = 2 * H * 128;
    const int D = H * 128;
    int wg = blockIdx.x * 8 + (threadIdx.x >> 5);
    int node = wg / H;
    int h = wg % H;
    if (node >= NN) return;
    int lane = threadIdx.x & 31;
    int cbase = h * 128 + lane * 4;

    float4 rv = *(const float4*)(xlr + (size_t)node * S + D + cbase);
    float4 av = *(const float4*)(att + cbase);
    int s = g_off[node], e = g_off[node + 1];

    float m = -1e30f, den = 0.f;
    float4 acc = make_float4(0.f, 0.f, 0.f, 0.f);

    // 1-deep prefetch
    float4 xv = make_float4(0.f, 0.f, 0.f, 0.f);
    if (s < e) {
        int src0 = g_csr_src[s];
        xv = *(const float4*)(xlr + (size_t)src0 * S + cbase);
    }
    for (int j = s; j < e; j++) {
        float4 cur = xv;
        if (j + 1 < e) {
            int srcn = g_csr_src[j + 1];
            xv = *(const float4*)(xlr + (size_t)srcn * S + cbase);
        }
        float t, p = 0.f;
        t = cur.x + rv.x; t = t > 0.f ? t : SLOPE * t; p += av.x * t;
        t = cur.y + rv.y; t = t > 0.f ? t : SLOPE * t; p += av.y * t;
        t = cur.z + rv.z; t = t > 0.f ? t : SLOPE * t; p += av.z * t;
        t = cur.w + rv.w; t = t > 0.f ? t : SLOPE * t; p += av.w * t;
#pragma unroll
        for (int o = 16; o; o >>= 1) p += __shfl_xor_sync(0xffffffffu, p, o);
        if (p > m) {
            float sc = __expf(m - p);
            den *= sc; acc.x *= sc; acc.y *= sc; acc.z *= sc; acc.w *= sc;
            m = p;
        }
        float w = __expf(p - m);
        den += w;
        acc.x += w * cur.x; acc.y += w * cur.y; acc.z += w * cur.z; acc.w += w * cur.w;
    }
    float inv = 1.f / den;
    float4 o4;
    float v;
    v = acc.x * inv + bias[cbase + 0]; o4.x = v > 0.f ? v : expm1f(v);
    v = acc.y * inv + bias[cbase + 1]; o4.y = v > 0.f ? v : expm1f(v);
    v = acc.z * inv + bias[cbase + 2]; o4.z = v > 0.f ? v : expm1f(v);
    v = acc.w * inv + bias[cbase + 3]; o4.w = v > 0.f ? v : expm1f(v);

    if (PERM) {
        // lane-pair swizzle into K-permuted order ([0,4,1,5,2,6,3,7] per 8-group)
        float r0 = __shfl_xor_sync(0xffffffffu, o4.x, 1);
        float r1 = __shfl_xor_sync(0xffffffffu, o4.y, 1);
        float r2 = __shfl_xor_sync(0xffffffffu, o4.z, 1);
        float r3 = __shfl_xor_sync(0xffffffffu, o4.w, 1);
        float4 w4;
        if ((lane & 1) == 0) w4 = make_float4(o4.x, r0, o4.y, r1);
        else                 w4 = make_float4(r2, o4.z, r3, o4.w);
        w4.x = f2tf32f(w4.x); w4.y = f2tf32f(w4.y);
        w4.z = f2tf32f(w4.z); w4.w = f2tf32f(w4.w);
        *(float4*)(out + (size_t)node * D + cbase) = w4;
    } else {
        *(float4*)(out + (size_t)node * D + cbase) = o4;
    }
}

// ----------------------------------------------------------------------------
// Pooling + MLP
// ----------------------------------------------------------------------------
__global__ void pool_kernel(const int* __restrict__ batch) {
    int i = blockIdx.x;
    int t = threadIdx.x;
    int b = batch[i];
    atomicAdd(&g_pool[b * HID + t], g_h3[(size_t)i * HID + t]);
    if (t == 0) atomicAdd(&g_cnt[b], 1.0f);
}
__global__ void mlp_kernel(const float* __restrict__ W1, const float* __restrict__ b1,
                           const float* __restrict__ W2, const float* __restrict__ b2,
                           float* __restrict__ out) {
    int g = blockIdx.x;
    int t = threadIdx.x;
    __shared__ float p[HID];
    __shared__ float hid[HID];
    __shared__ float red[HID];
    float c = fmaxf(g_cnt[g], 1.0f);
    p[t] = g_pool[g * HID + t] / c;
    __syncthreads();
    float a = 0.f;
    for (int k = 0; k < HID; k++) a += p[k] * W1[k * HID + t];
    hid[t] = fmaxf(a + b1[t], 0.f);
    __syncthreads();
    for (int o = 0; o < 2; o++) {
        red[t] = hid[t] * W2[t * 2 + o];
        __syncthreads();
        for (int stp = 64; stp; stp >>= 1) {
            if (t < stp) red[t] += red[t + stp];
            __syncthreads();
        }
        if (t == 0) out[g * 2 + o] = red[0] + b2[o];
        __syncthreads();
    }
}

// ----------------------------------------------------------------------------
// Launch
// ----------------------------------------------------------------------------
extern "C" void kernel_launch(void* const* d_in, const int* in_sizes, int n_in,
                              void* d_out, int out_size) {
    const float* x     = (const float*)d_in[0];
    const int*   esrc  = (const int*)d_in[1];
    const int*   edst  = (const int*)d_in[2];
    const int*   batch = (const int*)d_in[3];
    const float* Wl1 = (const float*)d_in[4];
    const float* Wr1 = (const float*)d_in[5];
    const float* bl1 = (const float*)d_in[6];
    const float* br1 = (const float*)d_in[7];
    const float* att1  = (const float*)d_in[8];
    const float* bias1 = (const float*)d_in[9];
    const float* Wl2 = (const float*)d_in[10];
    const float* Wr2 = (const float*)d_in[11];
    const float* bl2 = (const float*)d_in[12];
    const float* br2 = (const float*)d_in[13];
    const float* att2  = (const float*)d_in[14];
    const float* bias2 = (const float*)d_in[15];
    const float* Wl3 = (const float*)d_in[16];
    const float* Wr3 = (const float*)d_in[17];
    const float* bl3 = (const float*)d_in[18];
    const float* br3 = (const float*)d_in[19];
    const float* att3  = (const float*)d_in[20];
    const float* bias3 = (const float*)d_in[21];
    const float* Wm1 = (const float*)d_in[22];
    const float* bm1 = (const float*)d_in[23];
    const float* Wm2 = (const float*)d_in[24];
    const float* bm2 = (const float*)d_in[25];
    float* out = (float*)d_out;

    float *p_xlr, *p_h1, *p_h2, *p_h3, *p_xp, *p_wt;
    cudaGetSymbolAddress((void**)&p_xlr, g_xlr);
    cudaGetSymbolAddress((void**)&p_h1, g_h1);
    cudaGetSymbolAddress((void**)&p_h2, g_h2);
    cudaGetSymbolAddress((void**)&p_h3, g_h3);
    cudaGetSymbolAddress((void**)&p_xp, g_xp);
    cudaGetSymbolAddress((void**)&p_wt, g_wt);

    const int SMEM = 4 * SMEM_TILE * 4;  // 81920 bytes
    cudaFuncSetAttribute(gemm_mma, cudaFuncAttributeMaxDynamicSharedMemorySize, SMEM);

    // CSR build + x pre-pass
    zero_kernel<<<(NN + 255) / 256, 256>>>();
    hist_kernel<<<(ET + 255) / 256, 256>>>(edst);
    scan_kernel<<<1, 1024>>>();
    scatter_kernel<<<(ET + 255) / 256, 256>>>(esrc, edst);
    permute_x_kernel<<<(NN * FIN + 255) / 256, 256>>>(x, p_xp);

    const int RT = (NN + 127) / 128;  // 157 row tiles
    dim3 tb(32, 8);

    // Layer 1: K=128, fused Mout=1024
    transpose_kernel<<<dim3(16, 4), tb>>>(Wl1, p_wt, 128, 512);
    transpose_kernel<<<dim3(16, 4), tb>>>(Wr1, p_wt + 512 * 128, 128, 512);
    gemm_mma<<<dim3(RT, 8), 256, SMEM>>>(p_xp, p_wt, bl1, br1, p_xlr, NN, 128, 1024, 512);
    gatv2_fused<HEADS, true><<<(NN * HEADS + 7) / 8, 256>>>(p_xlr, att1, bias1, p_h1);

    // Layer 2: K=512, fused Mout=1024
    transpose_kernel<<<dim3(16, 16), tb>>>(Wl2, p_wt, 512, 512);
    transpose_kernel<<<dim3(16, 16), tb>>>(Wr2, p_wt + 512 * 512, 512, 512);
    gemm_mma<<<dim3(RT, 8), 256, SMEM>>>(p_h1, p_wt, bl2, br2, p_xlr, NN, 512, 1024, 512);
    gatv2_fused<HEADS, true><<<(NN * HEADS + 7) / 8, 256>>>(p_xlr, att2, bias2, p_h2);

    // Layer 3: K=512, fused Mout=256, single head
    transpose_kernel<<<dim3(4, 16), tb>>>(Wl3, p_wt, 512, 128);
    transpose_kernel<<<dim3(4, 16), tb>>>(Wr3, p_wt + 128 * 512, 512, 128);
    gemm_mma<<<dim3(RT, 2), 256, SMEM>>>(p_h2, p_wt, bl3, br3, p_xlr, NN, 512, 256, 128);
    gatv2_fused<1, false><<<(NN + 7) / 8, 256>>>(p_xlr, att3, bias3, p_h3);

    // Pool + MLP
    pool_kernel<<<NN, HID>>>(batch);
    mlp_kernel<<<BGR, HID>>>(Wm1, bm1, Wm2, bm2, out);
}

// round 7
// speedup vs baseline: 3.0009x; 1.0710x over previous
#include <cuda_runtime.h>
#include <cuda_bf16.h>
#include <cstdint>
#include <math.h>

#define NN    20000
#define EE    320000
#define ET    (EE + NN)
#define FIN   128
#define HID   128
#define HEADS 4
#define DBIG  (HEADS * HID)
#define BGR   64
#define SLOPE 0.2f

// ----------------------------------------------------------------------------
// Scratch (device globals)
// ----------------------------------------------------------------------------
__device__ float g_xlr[(size_t)NN * 1024];   // fused [xl | xr] output (natural order)
__device__ float g_h1[(size_t)NN * DBIG];    // K-permuted + tf32-rounded
__device__ float g_h2[(size_t)NN * DBIG];    // K-permuted + tf32-rounded
__device__ float g_h3[(size_t)NN * HID];     // natural
__device__ float g_xp[(size_t)NN * FIN];     // x, K-permuted + tf32-rounded
__device__ float g_wt[1024 * 512];           // fused transposed weights (K-permuted, tf32)
__device__ int   g_deg[NN];
__device__ int   g_off[NN + 1];
__device__ int   g_cursor[NN];
__device__ int   g_csr_src[ET];
__device__ float g_pool[BGR * HID];

// ----------------------------------------------------------------------------
// Helpers
// ----------------------------------------------------------------------------
__device__ __forceinline__ uint32_t f2tf32(float f) {
    uint32_t u;
    asm("cvt.rna.tf32.f32 %0, %1;" : "=r"(u) : "f"(f));
    return u;
}
__device__ __forceinline__ float f2tf32f(float f) { return __uint_as_float(f2tf32(f)); }
// K-permutation within each 8-group: [0,4,1,5,2,6,3,7]
__device__ __forceinline__ int kperm(int k) {
    return (k & ~7) | (((k & 3) << 1) | ((k >> 2) & 1));
}
__device__ __forceinline__ uint32_t smem_u32(const void* p) {
    uint32_t a;
    asm("{ .reg .u64 t; cvta.to.shared.u64 t, %1; cvt.u32.u64 %0, t; }" : "=r"(a) : "l"(p));
    return a;
}
__device__ __forceinline__ void cp_async16(uint32_t dst, const void* src) {
    asm volatile("cp.async.cg.shared.global [%0], [%1], 16;" :: "r"(dst), "l"(src) : "memory");
}
__device__ __forceinline__ void cp_commit() {
    asm volatile("cp.async.commit_group;" ::: "memory");
}
template <int N>
__device__ __forceinline__ void cp_wait() {
    asm volatile("cp.async.wait_group %0;" :: "n"(N) : "memory");
}

// ----------------------------------------------------------------------------
// CSR build
// ----------------------------------------------------------------------------
__global__ void zero_kernel() {
    int i = blockIdx.x * blockDim.x + threadIdx.x;
    if (i < NN) g_deg[i] = 0;
}
__global__ void hist_kernel(const int* __restrict__ edst) {
    int e = blockIdx.x * blockDim.x + threadIdx.x;
    if (e >= ET) return;
    int d = (e < EE) ? edst[e] : (e - EE);
    atomicAdd(&g_deg[d], 1);
}
__global__ void scan_kernel() {
    __shared__ int part[1024];
    int t = threadIdx.x;
    const int chunk = (NN + 1023) / 1024;
    int beg = t * chunk, end = beg + chunk;
    if (end > NN) end = NN;
    int s = 0;
    for (int i = beg; i < end; i++) s += g_deg[i];
    part[t] = s;
    __syncthreads();
    for (int o = 1; o < 1024; o <<= 1) {
        int v = (t >= o) ? part[t - o] : 0;
        __syncthreads();
        part[t] += v;
        __syncthreads();
    }
    int run = (t == 0) ? 0 : part[t - 1];
    for (int i = beg; i < end; i++) {
        g_off[i] = run; g_cursor[i] = run; run += g_deg[i];
    }
    if (t == 1023) g_off[NN] = part[1023];
}
__global__ void scatter_kernel(const int* __restrict__ esrc, const int* __restrict__ edst) {
    int e = blockIdx.x * blockDim.x + threadIdx.x;
    if (e >= ET) return;
    int s, d;
    if (e < EE) { s = esrc[e]; d = edst[e]; }
    else        { s = e - EE;  d = e - EE; }
    int pos = atomicAdd(&g_cursor[d], 1);
    g_csr_src[pos] = s;
}

// ----------------------------------------------------------------------------
// x pre-pass: permute K within 8-groups + round to tf32
// ----------------------------------------------------------------------------
__global__ void permute_x_kernel(const float* __restrict__ x, float* __restrict__ xp) {
    int idx = blockIdx.x * blockDim.x + threadIdx.x;
    if (idx >= NN * FIN) return;
    int row = idx >> 7, k = idx & 127;
    xp[(size_t)row * FIN + kperm(k)] = f2tf32f(x[idx]);
}

// ----------------------------------------------------------------------------
// Weight transpose: WT[m][kperm(k)] = tf32(W[k][m])
// ----------------------------------------------------------------------------
__global__ void transpose_kernel(const float* __restrict__ W, float* __restrict__ WT,
                                 int K, int M) {
    __shared__ float t[32][33];
    int m0 = blockIdx.x * 32, k0 = blockIdx.y * 32;
    int tx = threadIdx.x, ty = threadIdx.y;
#pragma unroll
    for (int i = 0; i < 32; i += 8)
        t[ty + i][tx] = W[(size_t)(k0 + ty + i) * M + m0 + tx];
    __syncthreads();
    int kp = kperm(k0 + tx);
#pragma unroll
    for (int i = 0; i < 32; i += 8)
        WT[(size_t)(m0 + ty + i) * K + kp] = f2tf32f(t[tx][ty + i]);
}

// ----------------------------------------------------------------------------
// tf32 mma.sync GEMM, cp.async double-buffered, fragment-major K layout.
// ----------------------------------------------------------------------------
#define SM_STRIDE 40
#define SMEM_TILE (128 * SM_STRIDE)
__global__ __launch_bounds__(256, 2)
void gemm_mma(const float* __restrict__ A, const float* __restrict__ BT,
              const float* __restrict__ bias_l, const float* __restrict__ bias_r,
              float* __restrict__ C, int Nrows, int K, int Mout, int Mhalf) {
    extern __shared__ float sm[];
    float* smA = sm;                    // [2][128][40]
    float* smB = sm + 2 * SMEM_TILE;    // [2][128][40]
    uint32_t uA = smem_u32(smA);
    uint32_t uB = smem_u32(smB);

    int tid = threadIdx.x;
    int lane = tid & 31, wid = tid >> 5;
    int wm = wid & 1;
    int wn = wid >> 1;
    int g = lane >> 2, t = lane & 3;
    int brow = blockIdx.x * 128;
    int bcol = blockIdx.y * 128;

    int cprow = tid >> 3, cpc4 = (tid & 7) * 4;

    float acc[4][4][4];
#pragma unroll
    for (int a = 0; a < 4; a++)
#pragma unroll
        for (int b = 0; b < 4; b++)
#pragma unroll
            for (int c = 0; c < 4; c++) acc[a][b][c] = 0.f;

    const int NT = K >> 5;

    auto load_tile = [&](int kt, int buf) {
        int k0 = kt << 5;
#pragma unroll
        for (int i = 0; i < 4; i++) {
            int row = cprow + i * 32;
            int gr = brow + row; if (gr >= Nrows) gr = Nrows - 1;
            cp_async16(uA + (uint32_t)(buf * SMEM_TILE + row * SM_STRIDE + cpc4) * 4,
                       A + (size_t)gr * K + k0 + cpc4);
        }
#pragma unroll
        for (int i = 0; i < 4; i++) {
            int row = cprow + i * 32;
            cp_async16(uB + (uint32_t)(buf * SMEM_TILE + row * SM_STRIDE + cpc4) * 4,
                       BT + (size_t)(bcol + row) * K + k0 + cpc4);
        }
    };

    load_tile(0, 0);
    cp_commit();

    for (int kt = 0; kt < NT; kt++) {
        int buf = kt & 1;
        if (kt + 1 < NT) {
            load_tile(kt + 1, (kt + 1) & 1);
            cp_commit();
            cp_wait<1>();
        } else {
            cp_wait<0>();
        }
        __syncthreads();

        const float* Ab = smA + buf * SMEM_TILE;
        const float* Bb = smB + buf * SMEM_TILE;
#pragma unroll
        for (int kk = 0; kk < 32; kk += 8) {
            uint32_t af[4][4], bf[4][2];
#pragma unroll
            for (int mt = 0; mt < 4; mt++) {
                int r = wm * 64 + mt * 16 + g;
                uint2 x0 = *(const uint2*)(Ab + r * SM_STRIDE + kk + 2 * t);
                uint2 x1 = *(const uint2*)(Ab + (r + 8) * SM_STRIDE + kk + 2 * t);
                af[mt][0] = x0.x;
                af[mt][1] = x1.x;
                af[mt][2] = x0.y;
                af[mt][3] = x1.y;
            }
#pragma unroll
            for (int nt = 0; nt < 4; nt++) {
                int n = wn * 32 + nt * 8 + g;
                uint2 b = *(const uint2*)(Bb + n * SM_STRIDE + kk + 2 * t);
                bf[nt][0] = b.x;
                bf[nt][1] = b.y;
            }
#pragma unroll
            for (int mt = 0; mt < 4; mt++)
#pragma unroll
                for (int nt = 0; nt < 4; nt++) {
                    asm volatile(
                        "mma.sync.aligned.m16n8k8.row.col.f32.tf32.tf32.f32 "
                        "{%0,%1,%2,%3}, {%4,%5,%6,%7}, {%8,%9}, {%0,%1,%2,%3};"
                        : "+f"(acc[mt][nt][0]), "+f"(acc[mt][nt][1]),
                          "+f"(acc[mt][nt][2]), "+f"(acc[mt][nt][3])
                        : "r"(af[mt][0]), "r"(af[mt][1]), "r"(af[mt][2]), "r"(af[mt][3]),
                          "r"(bf[nt][0]), "r"(bf[nt][1]));
                }
        }
        __syncthreads();
    }

#pragma unroll
    for (int mt = 0; mt < 4; mt++) {
        int r0 = brow + wm * 64 + mt * 16 + g;
#pragma unroll
        for (int nt = 0; nt < 4; nt++) {
            int c = bcol + wn * 32 + nt * 8 + 2 * t;
            float b0, b1;
            if (c < Mhalf) { b0 = bias_l[c]; b1 = bias_l[c + 1]; }
            else           { b0 = bias_r[c - Mhalf]; b1 = bias_r[c - Mhalf + 1]; }
            if (r0 < Nrows) {
                float2 v = make_float2(acc[mt][nt][0] + b0, acc[mt][nt][1] + b1);
                *(float2*)(C + (size_t)r0 * Mout + c) = v;
            }
            if (r0 + 8 < Nrows) {
                float2 v = make_float2(acc[mt][nt][2] + b0, acc[mt][nt][3] + b1);
                *(float2*)(C + (size_t)(r0 + 8) * Mout + c) = v;
            }
        }
    }
}

// ----------------------------------------------------------------------------
// Fused GATv2 attention (online softmax), 2-edge ILP: one warp per (node, head).
// ----------------------------------------------------------------------------
template <int H, bool PERM>
__global__ __launch_bounds__(256)
void gatv2_fused(const float* __restrict__ xlr,
                 const float* __restrict__ att, const float* __restrict__ bias,
                 float* __restrict__ out) {
    const int S = 2 * H * 128;
    const int D = H * 128;
    int wg = blockIdx.x * 8 + (threadIdx.x >> 5);
    int node = wg / H;
    int h = wg % H;
    if (node >= NN) return;
    int lane = threadIdx.x & 31;
    int cbase = h * 128 + lane * 4;

    float4 rv = *(const float4*)(xlr + (size_t)node * S + D + cbase);
    float4 av = *(const float4*)(att + cbase);
    int s = g_off[node], e = g_off[node + 1];

    float m = -1e30f, den = 0.f;
    float4 acc = make_float4(0.f, 0.f, 0.f, 0.f);

    int j = s;
    for (; j + 2 <= e; j += 2) {
        int s0 = g_csr_src[j], s1 = g_csr_src[j + 1];
        float4 x0 = *(const float4*)(xlr + (size_t)s0 * S + cbase);
        float4 x1 = *(const float4*)(xlr + (size_t)s1 * S + cbase);
        float t0, t1, p0 = 0.f, p1 = 0.f;
        t0 = x0.x + rv.x; t0 = t0 > 0.f ? t0 : SLOPE * t0; p0 += av.x * t0;
        t1 = x1.x + rv.x; t1 = t1 > 0.f ? t1 : SLOPE * t1; p1 += av.x * t1;
        t0 = x0.y + rv.y; t0 = t0 > 0.f ? t0 : SLOPE * t0; p0 += av.y * t0;
        t1 = x1.y + rv.y; t1 = t1 > 0.f ? t1 : SLOPE * t1; p1 += av.y * t1;
        t0 = x0.z + rv.z; t0 = t0 > 0.f ? t0 : SLOPE * t0; p0 += av.z * t0;
        t1 = x1.z + rv.z; t1 = t1 > 0.f ? t1 : SLOPE * t1; p1 += av.z * t1;
        t0 = x0.w + rv.w; t0 = t0 > 0.f ? t0 : SLOPE * t0; p0 += av.w * t0;
        t1 = x1.w + rv.w; t1 = t1 > 0.f ? t1 : SLOPE * t1; p1 += av.w * t1;
#pragma unroll
        for (int o = 16; o; o >>= 1) {
            p0 += __shfl_xor_sync(0xffffffffu, p0, o);
            p1 += __shfl_xor_sync(0xffffffffu, p1, o);
        }
        float mm = fmaxf(m, fmaxf(p0, p1));
        float sc = __expf(m - mm);
        m = mm;
        den *= sc; acc.x *= sc; acc.y *= sc; acc.z *= sc; acc.w *= sc;
        float w0 = __expf(p0 - m), w1 = __expf(p1 - m);
        den += w0 + w1;
        acc.x += w0 * x0.x + w1 * x1.x;
        acc.y += w0 * x0.y + w1 * x1.y;
        acc.z += w0 * x0.z + w1 * x1.z;
        acc.w += w0 * x0.w + w1 * x1.w;
    }
    if (j < e) {
        int s0 = g_csr_src[j];
        float4 x0 = *(const float4*)(xlr + (size_t)s0 * S + cbase);
        float t0, p0 = 0.f;
        t0 = x0.x + rv.x; t0 = t0 > 0.f ? t0 : SLOPE * t0; p0 += av.x * t0;
        t0 = x0.y + rv.y; t0 = t0 > 0.f ? t0 : SLOPE * t0; p0 += av.y * t0;
        t0 = x0.z + rv.z; t0 = t0 > 0.f ? t0 : SLOPE * t0; p0 += av.z * t0;
        t0 = x0.w + rv.w; t0 = t0 > 0.f ? t0 : SLOPE * t0; p0 += av.w * t0;
#pragma unroll
        for (int o = 16; o; o >>= 1) p0 += __shfl_xor_sync(0xffffffffu, p0, o);
        float mm = fmaxf(m, p0);
        float sc = __expf(m - mm);
        m = mm;
        den *= sc; acc.x *= sc; acc.y *= sc; acc.z *= sc; acc.w *= sc;
        float w0 = __expf(p0 - m);
        den += w0;
        acc.x += w0 * x0.x; acc.y += w0 * x0.y; acc.z += w0 * x0.z; acc.w += w0 * x0.w;
    }

    float inv = 1.f / den;
    float4 o4;
    float v;
    v = acc.x * inv + bias[cbase + 0]; o4.x = v > 0.f ? v : expm1f(v);
    v = acc.y * inv + bias[cbase + 1]; o4.y = v > 0.f ? v : expm1f(v);
    v = acc.z * inv + bias[cbase + 2]; o4.z = v > 0.f ? v : expm1f(v);
    v = acc.w * inv + bias[cbase + 3]; o4.w = v > 0.f ? v : expm1f(v);

    if (PERM) {
        float r0 = __shfl_xor_sync(0xffffffffu, o4.x, 1);
        float r1 = __shfl_xor_sync(0xffffffffu, o4.y, 1);
        float r2 = __shfl_xor_sync(0xffffffffu, o4.z, 1);
        float r3 = __shfl_xor_sync(0xffffffffu, o4.w, 1);
        float4 w4;
        if ((lane & 1) == 0) w4 = make_float4(o4.x, r0, o4.y, r1);
        else                 w4 = make_float4(r2, o4.z, r3, o4.w);
        w4.x = f2tf32f(w4.x); w4.y = f2tf32f(w4.y);
        w4.z = f2tf32f(w4.z); w4.w = f2tf32f(w4.w);
        *(float4*)(out + (size_t)node * D + cbase) = w4;
    } else {
        *(float4*)(out + (size_t)node * D + cbase) = o4;
    }
}

// ----------------------------------------------------------------------------
// Pooling (batch is sorted -> contiguous segments, no atomics) + MLP
// ----------------------------------------------------------------------------
__global__ void pool_kernel(const int* __restrict__ batch) {
    int g = blockIdx.x;
    int t = threadIdx.x;
    __shared__ int seg[2];
    if (t < 2) {
        int target = g + t;        // lower_bound(batch, target)
        int lo = 0, hi = NN;
        while (lo < hi) {
            int mid = (lo + hi) >> 1;
            if (batch[mid] < target) lo = mid + 1; else hi = mid;
        }
        seg[t] = lo;
    }
    __syncthreads();
    int lo = seg[0], hi = seg[1];
    float sum = 0.f;
    for (int i = lo; i < hi; i++) sum += g_h3[(size_t)i * HID + t];
    float c = fmaxf((float)(hi - lo), 1.0f);
    g_pool[g * HID + t] = sum / c;
}
__global__ void mlp_kernel(const float* __restrict__ W1, const float* __restrict__ b1,
                           const float* __restrict__ W2, const float* __restrict__ b2,
                           float* __restrict__ out) {
    int g = blockIdx.x;
    int t = threadIdx.x;
    __shared__ float p[HID];
    __shared__ float hid[HID];
    __shared__ float red[HID];
    p[t] = g_pool[g * HID + t];
    __syncthreads();
    float a = 0.f;
    for (int k = 0; k < HID; k++) a += p[k] * W1[k * HID + t];
    hid[t] = fmaxf(a + b1[t], 0.f);
    __syncthreads();
    for (int o = 0; o < 2; o++) {
        red[t] = hid[t] * W2[t * 2 + o];
        __syncthreads();
        for (int stp = 64; stp; stp >>= 1) {
            if (t < stp) red[t] += red[t + stp];
            __syncthreads();
        }
        if (t == 0) out[g * 2 + o] = red[0] + b2[o];
        __syncthreads();
    }
}

// ----------------------------------------------------------------------------
// Launch
// ----------------------------------------------------------------------------
extern "C" void kernel_launch(void* const* d_in, const int* in_sizes, int n_in,
                              void* d_out, int out_size) {
    const float* x     = (const float*)d_in[0];
    const int*   esrc  = (const int*)d_in[1];
    const int*   edst  = (const int*)d_in[2];
    const int*   batch = (const int*)d_in[3];
    const float* Wl1 = (const float*)d_in[4];
    const float* Wr1 = (const float*)d_in[5];
    const float* bl1 = (const float*)d_in[6];
    const float* br1 = (const float*)d_in[7];
    const float* att1  = (const float*)d_in[8];
    const float* bias1 = (const float*)d_in[9];
    const float* Wl2 = (const float*)d_in[10];
    const float* Wr2 = (const float*)d_in[11];
    const float* bl2 = (const float*)d_in[12];
    const float* br2 = (const float*)d_in[13];
    const float* att2  = (const float*)d_in[14];
    const float* bias2 = (const float*)d_in[15];
    const float* Wl3 = (const float*)d_in[16];
    const float* Wr3 = (const float*)d_in[17];
    const float* bl3 = (const float*)d_in[18];
    const float* br3 = (const float*)d_in[19];
    const float* att3  = (const float*)d_in[20];
    const float* bias3 = (const float*)d_in[21];
    const float* Wm1 = (const float*)d_in[22];
    const float* bm1 = (const float*)d_in[23];
    const float* Wm2 = (const float*)d_in[24];
    const float* bm2 = (const float*)d_in[25];
    float* out = (float*)d_out;

    float *p_xlr, *p_h1, *p_h2, *p_h3, *p_xp, *p_wt;
    cudaGetSymbolAddress((void**)&p_xlr, g_xlr);
    cudaGetSymbolAddress((void**)&p_h1, g_h1);
    cudaGetSymbolAddress((void**)&p_h2, g_h2);
    cudaGetSymbolAddress((void**)&p_h3, g_h3);
    cudaGetSymbolAddress((void**)&p_xp, g_xp);
    cudaGetSymbolAddress((void**)&p_wt, g_wt);

    const int SMEM = 4 * SMEM_TILE * 4;  // 81920 bytes
    cudaFuncSetAttribute(gemm_mma, cudaFuncAttributeMaxDynamicSharedMemorySize, SMEM);

    const int RT = (NN + 127) / 128;  // 157 row tiles
    dim3 tb(32, 8);

    // --- front: layer-1 GEMM path first (gemm_mma at stream position 4 for ncu) ---
    permute_x_kernel<<<(NN * FIN + 255) / 256, 256>>>(x, p_xp);                 // 1
    transpose_kernel<<<dim3(16, 4), tb>>>(Wl1, p_wt, 128, 512);                 // 2
    transpose_kernel<<<dim3(16, 4), tb>>>(Wr1, p_wt + 512 * 128, 128, 512);     // 3
    gemm_mma<<<dim3(RT, 8), 256, SMEM>>>(p_xp, p_wt, bl1, br1, p_xlr,           // 4
                                         NN, 128, 1024, 512);

    // --- CSR build (only needed before attention) ---
    zero_kernel<<<(NN + 255) / 256, 256>>>();                                   // 5
    hist_kernel<<<(ET + 255) / 256, 256>>>(edst);                               // 6
    scan_kernel<<<1, 1024>>>();                                                 // 7
    scatter_kernel<<<(ET + 255) / 256, 256>>>(esrc, edst);                      // 8

    gatv2_fused<HEADS, true><<<(NN * HEADS + 7) / 8, 256>>>(p_xlr, att1, bias1, p_h1);

    // Layer 2
    transpose_kernel<<<dim3(16, 16), tb>>>(Wl2, p_wt, 512, 512);
    transpose_kernel<<<dim3(16, 16), tb>>>(Wr2, p_wt + 512 * 512, 512, 512);
    gemm_mma<<<dim3(RT, 8), 256, SMEM>>>(p_h1, p_wt, bl2, br2, p_xlr, NN, 512, 1024, 512);
    gatv2_fused<HEADS, true><<<(NN * HEADS + 7) / 8, 256>>>(p_xlr, att2, bias2, p_h2);

    // Layer 3
    transpose_kernel<<<dim3(4, 16), tb>>>(Wl3, p_wt, 512, 128);
    transpose_kernel<<<dim3(4, 16), tb>>>(Wr3, p_wt + 128 * 512, 512, 128);
    gemm_mma<<<dim3(RT, 2), 256, SMEM>>>(p_h2, p_wt, bl3, br3, p_xlr, NN, 512, 256, 128);
    gatv2_fused<1, false><<<(NN + 7) / 8, 256>>>(p_xlr, att3, bias3, p_h3);

    // Pool + MLP
    pool_kernel<<<BGR, HID>>>(batch);
    mlp_kernel<<<BGR, HID>>>(Wm1, bm1, Wm2, bm2, out);
}